// round 13
// baseline (speedup 1.0000x reference)
#include <cuda_runtime.h>
#include <cuda_bf16.h>
#include <cstdint>

// Problem constants
#define U_DIM 20000
#define I_DIM 10000
#define K_DIM 64
#define B_DIM 4096

// Output regions (floats), reference return order.
#define OFF_SHAT   0LL
#define N_SHAT     (200000000LL)                 // U*I
#define OFF_UF     (OFF_SHAT + N_SHAT)           // 200,000,000
#define N_UF       (1280000LL)
#define OFF_UB     (OFF_UF + N_UF)               // 201,280,000
#define N_UB       (20000LL)
#define OFF_IF     (OFF_UB + N_UB)               // 201,300,000
#define N_IF       (640000LL)
#define OFF_IB     (OFF_IF + N_IF)               // 201,940,000
#define N_IB       (10000LL)
#define N_TOTAL    (OFF_IB + N_IB)               // 201,950,000

__device__ __forceinline__ float warp_sum(float s) {
    #pragma unroll
    for (int off = 16; off; off >>= 1)
        s += __shfl_xor_sync(0xffffffffu, s, off);
    return s;
}

// ---------------------------------------------------------------------------
// Scatter (PDL attrs kept; after a memset node it degrades gracefully to
// normal stream ordering). One warp per batch entry. Prologue: index loads,
// random row gathers, dot product, bias loads. cudaGridDependencySynchronize
// guarantees the preceding zeros are visible. Then the scattered stores.
// Duplicate u/i/(u,i) across entries write identical values (benign race).
// ---------------------------------------------------------------------------
__global__ void __launch_bounds__(256)
mmf_scatter_pdl(const float* __restrict__ P,   // [U,K]
                const float* __restrict__ Q,   // [I,K]
                const float* __restrict__ bu,  // [U]
                const float* __restrict__ bi,  // [I]
                const int* __restrict__ uidx,  // [B] i32
                const int* __restrict__ iidx,  // [B] i32
                float* __restrict__ out) {
    int g    = blockIdx.x * blockDim.x + threadIdx.x;
    int e    = g >> 5;                         // entry = warp id
    int lane = g & 31;

    // ---- phase 1: all loads + compute ----
    int u = __ldg(&uidx[e]);
    int i = __ldg(&iidx[e]);

    const float2* pu = reinterpret_cast<const float2*>(P + (long long)u * K_DIM);
    const float2* qi = reinterpret_cast<const float2*>(Q + (long long)i * K_DIM);
    float2 a = __ldg(&pu[lane]);
    float2 b = __ldg(&qi[lane]);

    float s = warp_sum(fmaf(a.x, b.x, a.y * b.y));
    float bias_u = __ldg(&bu[u]);
    float bias_i = __ldg(&bi[i]);

    float2* uf  = reinterpret_cast<float2*>(out + OFF_UF + (long long)u * K_DIM);
    float2* ifr = reinterpret_cast<float2*>(out + OFF_IF + (long long)i * K_DIM);

    // ---- wait for the preceding zeros to be globally visible ----
    cudaGridDependencySynchronize();

    // ---- phase 2: scattered stores ----
    uf[lane]  = a;
    ifr[lane] = b;
    if (lane == 0) {
        out[OFF_UB + u] = bias_u;
        out[OFF_IB + i] = bias_i;
        out[(long long)u * I_DIM + i] = s + bias_u + bias_i;
    }
}

// ---------------------------------------------------------------------------
// Launch. inputs: P [U,K] f32, Q [I,K] f32, bu [U,1] f32, bi [I] f32,
// users_idx [B] int32, items_idx [B] int32
// ---------------------------------------------------------------------------
extern "C" void kernel_launch(void* const* d_in, const int* in_sizes, int n_in,
                              void* d_out, int out_size) {
    const float* P    = (const float*)d_in[0];
    const float* Q    = (const float*)d_in[1];
    const float* bu   = (const float*)d_in[2];
    const float* bi   = (const float*)d_in[3];
    const int*   uidx = (const int*)d_in[4];
    const int*   iidx = (const int*)d_in[5];
    float* out = (float*)d_out;

    // 1) zero everything via the driver's memset path (graph-capturable
    //    memset node; A/B test against the 7.37 TB/s custom sweep).
    cudaMemsetAsync(out, 0, (size_t)out_size * sizeof(float), 0);

    // 2) scatter (PDL attrs retained; safe after a memset node)
    cudaLaunchConfig_t cfg = {};
    cfg.gridDim  = dim3((B_DIM * 32) / 256, 1, 1);   // 512 blocks
    cfg.blockDim = dim3(256, 1, 1);
    cudaLaunchAttribute attrs[1];
    attrs[0].id = cudaLaunchAttributeProgrammaticStreamSerialization;
    attrs[0].val.programmaticStreamSerializationAllowed = 1;
    cfg.attrs = attrs;
    cfg.numAttrs = 1;
    cudaLaunchKernelEx(&cfg, mmf_scatter_pdl, P, Q, bu, bi, uidx, iidx, out);
}

// round 14
// speedup vs baseline: 1.0358x; 1.0358x over previous
#include <cuda_runtime.h>
#include <cuda_bf16.h>
#include <cstdint>

// Problem constants
#define U_DIM 20000
#define I_DIM 10000
#define K_DIM 64
#define B_DIM 4096

// Output regions (floats), reference return order.
#define OFF_SHAT   0LL
#define N_SHAT     (200000000LL)                 // U*I
#define OFF_UF     (OFF_SHAT + N_SHAT)           // 200,000,000
#define N_UF       (1280000LL)
#define OFF_UB     (OFF_UF + N_UF)               // 201,280,000
#define N_UB       (20000LL)
#define OFF_IF     (OFF_UB + N_UB)               // 201,300,000
#define N_IF       (640000LL)
#define OFF_IB     (OFF_IF + N_IF)               // 201,940,000
#define N_IB       (10000LL)
#define N_TOTAL    (OFF_IB + N_IB)               // 201,950,000 (divisible by 4)

#define N4_SHAT    (N_SHAT / 4)                  // 50,000,000 float4s
#define N4_TAIL    ((N_TOTAL - N_SHAT) / 4)      // 487,500 float4s (regions 2-5)

// ---------------------------------------------------------------------------
// Scratch: S_hat sparse patches, rewritten identically every call.
// ---------------------------------------------------------------------------
__device__ int   g_loc[B_DIM];   // flat S_hat index u*I+i (< 2^31)
__device__ float g_val[B_DIM];   // dot + bu + bi

__device__ __forceinline__ float warp_sum(float s) {
    #pragma unroll
    for (int off = 16; off; off >>= 1)
        s += __shfl_xor_sync(0xffffffffu, s, off);
    return s;
}

// ---------------------------------------------------------------------------
// Z2: zero regions 2-5 only (7.8 MB). Pure stores.
// ---------------------------------------------------------------------------
__global__ void __launch_bounds__(256)
mmf_zero_tail(float4* __restrict__ t4) {        // t4 = out + OFF_UF
    long long idx = (long long)blockIdx.x * blockDim.x + threadIdx.x;
    if (idx < N4_TAIL) t4[idx] = make_float4(0.f, 0.f, 0.f, 0.f);
}

// ---------------------------------------------------------------------------
// scatter25 (PDL dependent of Z2; PDL primary of Z1 via EARLY trigger):
// prologue overlaps Z2; after gridsync, fills regions 2-5 rows/biases and
// stashes the 4096 S_hat (loc,val) pairs in scratch. Touches ONLY regions
// 2-5 + scratch — disjoint from Z1's S_hat sweep, so Z1 may run concurrently.
// Duplicate u/i across entries write identical values (benign race).
// ---------------------------------------------------------------------------
__global__ void __launch_bounds__(256)
mmf_scatter25(const float* __restrict__ P,   // [U,K]
              const float* __restrict__ Q,   // [I,K]
              const float* __restrict__ bu,  // [U]
              const float* __restrict__ bi,  // [I]
              const int* __restrict__ uidx,  // [B] i32
              const int* __restrict__ iidx,  // [B] i32
              float* __restrict__ out) {
    // let Z1 (disjoint sweep) launch immediately — small kernel, cheap trigger
    cudaTriggerProgrammaticLaunchCompletion();

    int g    = blockIdx.x * blockDim.x + threadIdx.x;
    int e    = g >> 5;                         // entry = warp id
    int lane = g & 31;

    // ---- prologue: loads + dot (overlaps Z2) ----
    int u = __ldg(&uidx[e]);
    int i = __ldg(&iidx[e]);

    const float2* pu = reinterpret_cast<const float2*>(P + (long long)u * K_DIM);
    const float2* qi = reinterpret_cast<const float2*>(Q + (long long)i * K_DIM);
    float2 a = __ldg(&pu[lane]);
    float2 b = __ldg(&qi[lane]);

    float s = warp_sum(fmaf(a.x, b.x, a.y * b.y));
    float bias_u = __ldg(&bu[u]);
    float bias_i = __ldg(&bi[i]);

    float2* uf  = reinterpret_cast<float2*>(out + OFF_UF + (long long)u * K_DIM);
    float2* ifr = reinterpret_cast<float2*>(out + OFF_IF + (long long)i * K_DIM);

    // ---- wait for Z2's zeros to be visible ----
    cudaGridDependencySynchronize();

    // ---- stores into regions 2-5 + scratch ----
    uf[lane]  = a;
    ifr[lane] = b;
    if (lane == 0) {
        out[OFF_UB + u] = bias_u;
        out[OFF_IB + i] = bias_i;
        g_loc[e] = u * I_DIM + i;
        g_val[e] = s + bias_u + bias_i;
    }
}

// ---------------------------------------------------------------------------
// Z1: zero S_hat (800 MB). The proven pure-store sweep — NO loads, NO fences,
// NO atomics, NO trigger, NO gridsync (it depends on nothing memory-wise;
// the PDL attribute only lets it START while scatter25 finishes).
// ---------------------------------------------------------------------------
__global__ void mmf_zero_shat(float4* __restrict__ out4) {
    long long idx = (long long)blockIdx.x * blockDim.x + threadIdx.x;
    if (idx < N4_SHAT) out4[idx] = make_float4(0.f, 0.f, 0.f, 0.f);
}

// ---------------------------------------------------------------------------
// tinyT (PDL dependent of Z1): 4096 scalar S_hat patches from scratch.
// Prologue loads overlap Z1's teardown; gridsync; one store per thread.
// ---------------------------------------------------------------------------
__global__ void __launch_bounds__(256)
mmf_patch_shat(float* __restrict__ out) {
    int e = blockIdx.x * blockDim.x + threadIdx.x;   // 0..4095
    int   loc = g_loc[e];
    float val = g_val[e];
    cudaGridDependencySynchronize();                 // Z1's zeros visible
    out[loc] = val;                                  // dup pairs: same value
}

// ---------------------------------------------------------------------------
// Launch. inputs: P [U,K] f32, Q [I,K] f32, bu [U,1] f32, bi [I] f32,
// users_idx [B] int32, items_idx [B] int32
// ---------------------------------------------------------------------------
extern "C" void kernel_launch(void* const* d_in, const int* in_sizes, int n_in,
                              void* d_out, int out_size) {
    const float* P    = (const float*)d_in[0];
    const float* Q    = (const float*)d_in[1];
    const float* bu   = (const float*)d_in[2];
    const float* bi   = (const float*)d_in[3];
    const int*   uidx = (const int*)d_in[4];
    const int*   iidx = (const int*)d_in[5];
    float* out = (float*)d_out;

    cudaLaunchAttribute pdl[1];
    pdl[0].id = cudaLaunchAttributeProgrammaticStreamSerialization;
    pdl[0].val.programmaticStreamSerializationAllowed = 1;

    // 1) Z2: zero regions 2-5 (7.8 MB)
    const int z2blocks = (int)((N4_TAIL + 255) / 256);          // 1905
    mmf_zero_tail<<<z2blocks, 256>>>(
        reinterpret_cast<float4*>(out + OFF_UF));

    // 2) scatter25 (PDL after Z2; triggers early so Z1 overlaps it)
    {
        cudaLaunchConfig_t cfg = {};
        cfg.gridDim  = dim3((B_DIM * 32) / 256, 1, 1);          // 512 blocks
        cfg.blockDim = dim3(256, 1, 1);
        cfg.attrs = pdl; cfg.numAttrs = 1;
        cudaLaunchKernelEx(&cfg, mmf_scatter25, P, Q, bu, bi, uidx, iidx, out);
    }

    // 3) Z1: the 800 MB S_hat sweep (PDL: starts during scatter25)
    {
        cudaLaunchConfig_t cfg = {};
        cfg.gridDim  = dim3((unsigned)((N4_SHAT + 255) / 256), 1, 1); // 195,313
        cfg.blockDim = dim3(256, 1, 1);
        cfg.attrs = pdl; cfg.numAttrs = 1;
        cudaLaunchKernelEx(&cfg, mmf_zero_shat, (float4*)out);
    }

    // 4) tinyT: patch the 4096 S_hat scalars (PDL after Z1)
    {
        cudaLaunchConfig_t cfg = {};
        cfg.gridDim  = dim3(B_DIM / 256, 1, 1);                 // 16 blocks
        cfg.blockDim = dim3(256, 1, 1);
        cfg.attrs = pdl; cfg.numAttrs = 1;
        cudaLaunchKernelEx(&cfg, mmf_patch_shat, out);
    }
}

// round 16
// speedup vs baseline: 1.0384x; 1.0025x over previous
#include <cuda_runtime.h>
#include <cuda_bf16.h>
#include <cstdint>

// Problem constants
#define U_DIM 20000
#define I_DIM 10000
#define K_DIM 64
#define B_DIM 4096

// Output regions (floats), reference return order.
#define OFF_SHAT   0LL
#define N_SHAT     (200000000LL)                 // U*I
#define OFF_UF     (OFF_SHAT + N_SHAT)           // 200,000,000
#define N_UF       (1280000LL)
#define OFF_UB     (OFF_UF + N_UF)               // 201,280,000
#define N_UB       (20000LL)
#define OFF_IF     (OFF_UB + N_UB)               // 201,300,000
#define N_IF       (640000LL)
#define OFF_IB     (OFF_IF + N_IF)               // 201,940,000
#define N_IB       (10000LL)
#define N_TOTAL    (OFF_IB + N_IB)               // 201,950,000 (divisible by 4)

#define N4_SHAT    (N_SHAT / 4)                  // 50,000,000 float4s
#define N4_TAIL    ((N_TOTAL - N_SHAT) / 4)      // 487,500 float4s (regions 2-5)

#define HASH_SLOTS 8192
#define HASH_MASK  (HASH_SLOTS - 1)

// ---------------------------------------------------------------------------
// Scratch. g_hash is zeroed by Z2 every call (replay-safe); g_loc/g_val are
// fully rewritten by scatter25 every call.
// ---------------------------------------------------------------------------
__device__ int   g_loc[B_DIM];       // flat S_hat index, or -1 (non-owner dup)
__device__ float g_val[B_DIM];       // dot + bu + bi
__device__ unsigned g_hash[HASH_SLOTS];

__device__ __forceinline__ float warp_sum(float s) {
    #pragma unroll
    for (int off = 16; off; off >>= 1)
        s += __shfl_xor_sync(0xffffffffu, s, off);
    return s;
}

// ---------------------------------------------------------------------------
// Z2: zero regions 2-5 (7.8 MB) AND the dedup hash (32 KB). Pure stores.
// ---------------------------------------------------------------------------
__global__ void __launch_bounds__(256)
mmf_zero_tail(float4* __restrict__ t4) {        // t4 = out + OFF_UF
    long long idx = (long long)blockIdx.x * blockDim.x + threadIdx.x;
    if (idx < N4_TAIL) t4[idx] = make_float4(0.f, 0.f, 0.f, 0.f);
    if (idx < HASH_SLOTS) g_hash[idx] = 0u;
}

// ---------------------------------------------------------------------------
// scatter25 (PDL dependent of Z2; early trigger so Z1 launches immediately):
// prologue overlaps Z2; gridsync; fills regions 2-5 rows/biases; dedups the
// 4096 S_hat targets via hash CAS (exactly one owner per unique address this
// call) and stashes (loc,val). Owner may differ per replay, but all owners of
// a key write identical val -> deterministic output.
// ---------------------------------------------------------------------------
__global__ void __launch_bounds__(256)
mmf_scatter25(const float* __restrict__ P,   // [U,K]
              const float* __restrict__ Q,   // [I,K]
              const float* __restrict__ bu,  // [U]
              const float* __restrict__ bi,  // [I]
              const int* __restrict__ uidx,  // [B] i32
              const int* __restrict__ iidx,  // [B] i32
              float* __restrict__ out) {
    cudaTriggerProgrammaticLaunchCompletion();   // let Z1 (disjoint) launch now

    int g    = blockIdx.x * blockDim.x + threadIdx.x;
    int e    = g >> 5;                         // entry = warp id
    int lane = g & 31;

    // ---- prologue: loads + dot (overlaps Z2) ----
    int u = __ldg(&uidx[e]);
    int i = __ldg(&iidx[e]);

    const float2* pu = reinterpret_cast<const float2*>(P + (long long)u * K_DIM);
    const float2* qi = reinterpret_cast<const float2*>(Q + (long long)i * K_DIM);
    float2 a = __ldg(&pu[lane]);
    float2 b = __ldg(&qi[lane]);

    float s = warp_sum(fmaf(a.x, b.x, a.y * b.y));
    float bias_u = __ldg(&bu[u]);
    float bias_i = __ldg(&bi[i]);

    float2* uf  = reinterpret_cast<float2*>(out + OFF_UF + (long long)u * K_DIM);
    float2* ifr = reinterpret_cast<float2*>(out + OFF_IF + (long long)i * K_DIM);

    // ---- wait for Z2 (regions 2-5 zeros + hash reset) ----
    cudaGridDependencySynchronize();

    // ---- stores into regions 2-5 + dedup/stash ----
    uf[lane]  = a;
    ifr[lane] = b;
    if (lane == 0) {
        out[OFF_UB + u] = bias_u;
        out[OFF_IB + i] = bias_i;

        int flat = u * I_DIM + i;                      // < 2^31
        unsigned key = (unsigned)flat + 1u;            // 0 = empty
        unsigned h = ((key * 2654435761u) >> 13) & HASH_MASK;
        bool own = false;
        for (;;) {
            unsigned prev = atomicCAS(&g_hash[h], 0u, key);
            if (prev == 0u) { own = true; break; }     // I inserted it
            if (prev == key) break;                    // duplicate, not owner
            h = (h + 1) & HASH_MASK;                   // collision, probe on
        }
        g_loc[e] = own ? flat : -1;
        g_val[e] = s + bias_u + bias_i;
    }
}

// ---------------------------------------------------------------------------
// Z1: zero S_hat (800 MB). Proven pure-store sweep — NO loads, NO fences,
// NO atomics, NO trigger, NO gridsync. PDL attr only lets it start during
// scatter25 (disjoint memory).
// ---------------------------------------------------------------------------
__global__ void mmf_zero_shat(float4* __restrict__ out4) {
    long long idx = (long long)blockIdx.x * blockDim.x + threadIdx.x;
    if (idx < N4_SHAT) out4[idx] = make_float4(0.f, 0.f, 0.f, 0.f);
}

// ---------------------------------------------------------------------------
// tinyT (PDL after Z1, NO gridsync): per-address ordering via strict
// spin-until-zero with L2-coherent loads. Observing 0 proves that address's
// zero reached L2 (coherence point); the same-thread store afterwards
// serializes after it. Dedup guarantees exactly one patcher per address,
// so the spin cannot be defeated by another patcher's store (no deadlock,
// no stale-early-exit). Avoids waiting for Z1's global store drain.
// ---------------------------------------------------------------------------
__global__ void __launch_bounds__(256)
mmf_patch_shat(float* __restrict__ out) {
    int e = blockIdx.x * blockDim.x + threadIdx.x;   // 0..4095
    int loc = g_loc[e];
    if (loc < 0) return;                             // duplicate, not owner
    unsigned tgt = __float_as_uint(g_val[e]);
    float* p = out + loc;
    unsigned x;
    for (;;) {
        asm volatile("ld.global.cv.b32 %0, [%1];" : "=r"(x) : "l"(p));
        if (x == 0u) break;
        __nanosleep(32);
    }
    asm volatile("st.global.b32 [%0], %1;" :: "l"(p), "r"(tgt) : "memory");
}

// ---------------------------------------------------------------------------
// Launch. inputs: P [U,K] f32, Q [I,K] f32, bu [U,1] f32, bi [I] f32,
// users_idx [B] int32, items_idx [B] int32
// ---------------------------------------------------------------------------
extern "C" void kernel_launch(void* const* d_in, const int* in_sizes, int n_in,
                              void* d_out, int out_size) {
    const float* P    = (const float*)d_in[0];
    const float* Q    = (const float*)d_in[1];
    const float* bu   = (const float*)d_in[2];
    const float* bi   = (const float*)d_in[3];
    const int*   uidx = (const int*)d_in[4];
    const int*   iidx = (const int*)d_in[5];
    float* out = (float*)d_out;

    cudaLaunchAttribute pdl[1];
    pdl[0].id = cudaLaunchAttributeProgrammaticStreamSerialization;
    pdl[0].val.programmaticStreamSerializationAllowed = 1;

    // 1) Z2: zero regions 2-5 + hash
    const int z2blocks = (int)((N4_TAIL + 255) / 256);          // 1905
    mmf_zero_tail<<<z2blocks, 256>>>(
        reinterpret_cast<float4*>(out + OFF_UF));

    // 2) scatter25 (PDL after Z2; early trigger so Z1 overlaps it)
    {
        cudaLaunchConfig_t cfg = {};
        cfg.gridDim  = dim3((B_DIM * 32) / 256, 1, 1);          // 512 blocks
        cfg.blockDim = dim3(256, 1, 1);
        cfg.attrs = pdl; cfg.numAttrs = 1;
        cudaLaunchKernelEx(&cfg, mmf_scatter25, P, Q, bu, bi, uidx, iidx, out);
    }

    // 3) Z1: the 800 MB S_hat sweep (PDL: starts during scatter25)
    {
        cudaLaunchConfig_t cfg = {};
        cfg.gridDim  = dim3((unsigned)((N4_SHAT + 255) / 256), 1, 1); // 195,313
        cfg.blockDim = dim3(256, 1, 1);
        cfg.attrs = pdl; cfg.numAttrs = 1;
        cudaLaunchKernelEx(&cfg, mmf_zero_shat, (float4*)out);
    }

    // 4) tinyT: patch the unique S_hat scalars (PDL after Z1, spin-ordered)
    {
        cudaLaunchConfig_t cfg = {};
        cfg.gridDim  = dim3(B_DIM / 256, 1, 1);                 // 16 blocks
        cfg.blockDim = dim3(256, 1, 1);
        cfg.attrs = pdl; cfg.numAttrs = 1;
        cudaLaunchKernelEx(&cfg, mmf_patch_shat, out);
    }
}